// round 7
// baseline (speedup 1.0000x reference)
#include <cuda_runtime.h>
#include <cuda_fp16.h>
#include <cstdint>

#define B_ 4
#define N_ 4096
#define F_ 64
#define BM 128
#define BK 32
#define NKT (N_ / BK)                  // 128
#define STAGES 4

// smem: T-only ring. One stage = 3 chains x 64 rows x 64B = 12288 B.
#define T_CH_B (F_ * 64)               // 4096
#define STAGE_BYTES (3 * T_CH_B)       // 12288
#define SMEM_BYTES (STAGES * STAGE_BYTES)   // 49152

// T scratch: g_T[c][b][n][k] = fp16_rne( (X[b] @ w_c)[k][n] )
__device__ __half g_T[3][B_][F_][N_];

// ---------------------------------------------------------------------------
__device__ __forceinline__ uint32_t smem_u32(const void* p) {
    uint32_t a;
    asm("{ .reg .u64 t; cvta.to.shared.u64 t, %1; cvt.u32.u64 %0, t; }"
        : "=r"(a) : "l"(p));
    return a;
}
__device__ __forceinline__ void ldsm4(uint32_t* r, uint32_t addr) {
    asm volatile("ldmatrix.sync.aligned.m8n8.x4.shared.b16 {%0,%1,%2,%3}, [%4];"
                 : "=r"(r[0]), "=r"(r[1]), "=r"(r[2]), "=r"(r[3]) : "r"(addr));
}
__device__ __forceinline__ void mma16816(float* d, const uint32_t* a,
                                         uint32_t b0, uint32_t b1) {
    asm volatile("mma.sync.aligned.m16n8k16.row.col.f32.f16.f16.f32 "
                 "{%0,%1,%2,%3}, {%4,%5,%6,%7}, {%8,%9}, {%0,%1,%2,%3};"
                 : "+f"(d[0]), "+f"(d[1]), "+f"(d[2]), "+f"(d[3])
                 : "r"(a[0]), "r"(a[1]), "r"(a[2]), "r"(a[3]), "r"(b0), "r"(b1));
}
__device__ __forceinline__ uint32_t packh2(float x, float y) {
    __half2 h = __floats2half2_rn(x, y);
    return *(uint32_t*)&h;
}

// ---------------------------------------------------------------------------
// Kernel 1: g_T[c][b][g][m] = fp16( sum_f X[b][m][f] * w_c[f][g] )
// (sW reads are warp-broadcast: all lanes of a warp share g0)
// ---------------------------------------------------------------------------
__global__ void __launch_bounds__(256)
compute_T_kernel(const float* __restrict__ X,
                 const float* __restrict__ w0,
                 const float* __restrict__ w1,
                 const float* __restrict__ w2) {
    const int c = blockIdx.z;
    const int b = blockIdx.y;
    const int m0 = blockIdx.x * 64;
    const float* w = (c == 0) ? w0 : (c == 1) ? w1 : w2;

    __shared__ float sX[64 * 68];
    __shared__ float sW[64 * 68];

    const int tid = threadIdx.x;
    {
        const int q = tid & 15;
        const int r = tid >> 4;
        #pragma unroll
        for (int j = 0; j < 4; j++) {
            const int row = r + 16 * j;
            *(float4*)(sX + row * 68 + q * 4) =
                *(const float4*)(X + ((size_t)b * N_ + m0 + row) * F_ + q * 4);
            *(float4*)(sW + row * 68 + q * 4) =
                *(const float4*)(w + (size_t)row * F_ + q * 4);
        }
    }
    __syncthreads();

    const int row = tid & 63;            // distinct per lane -> 1 wavefront
    const int g0  = (tid >> 6) * 16;     // uniform per warp -> broadcast

    float acc[16];
    #pragma unroll
    for (int i = 0; i < 16; i++) acc[i] = 0.f;

    #pragma unroll 8
    for (int f = 0; f < 64; f++) {
        const float x = sX[row * 68 + f];
        #pragma unroll
        for (int j = 0; j < 4; j++) {
            float4 wv = *(const float4*)(sW + f * 68 + g0 + j * 4);
            acc[j * 4 + 0] += x * wv.x;
            acc[j * 4 + 1] += x * wv.y;
            acc[j * 4 + 2] += x * wv.z;
            acc[j * 4 + 3] += x * wv.w;
        }
    }
    __syncthreads();

    #pragma unroll
    for (int j = 0; j < 4; j++)
        *(float4*)(sX + row * 68 + g0 + j * 4) =
            make_float4(acc[j*4+0], acc[j*4+1], acc[j*4+2], acc[j*4+3]);
    __syncthreads();

    const int g  = tid >> 2;
    const int ms = (tid & 3) * 16;
    uint32_t h[8];
    #pragma unroll
    for (int i = 0; i < 8; i++)
        h[i] = packh2(sX[(ms + 2*i) * 68 + g], sX[(ms + 2*i + 1) * 68 + g]);
    __half* out = &g_T[c][b][g][m0 + ms];
    ((uint4*)out)[0] = make_uint4(h[0], h[1], h[2], h[3]);
    ((uint4*)out)[1] = make_uint4(h[4], h[5], h[6], h[7]);
}

// ---------------------------------------------------------------------------
// Kernel 2: Y[b] = relu(A0@T0 + A1@T1 + A2@T2)
// grid (32, 4) = 128 CTAs, block 256 (8 warps, warp tile 16x64).
// A fragments: direct GMEM->register (__ldcs float2), prefetched 1 k-tile ahead.
// T: 4-stage cp.async smem ring + ldmatrix.
// ---------------------------------------------------------------------------
__global__ void __launch_bounds__(256)
gnn_main_kernel(const float* __restrict__ A0,
                const float* __restrict__ A1,
                const float* __restrict__ A2,
                float* __restrict__ Y) {
    extern __shared__ char smem[];
    const uint32_t sb = smem_u32(smem);
    const int tid = threadIdx.x;
    const int b = blockIdx.y;
    const int rowBase = blockIdx.x * BM;

    const float* Ap[3];
    Ap[0] = A0 + (size_t)b * N_ * N_;
    Ap[1] = A1 + (size_t)b * N_ * N_;
    Ap[2] = A2 + (size_t)b * N_ * N_;

    const int lane = tid & 31;
    const int warp = tid >> 5;

    // per-warp A fragment base pointers: row r0 = rowBase + warp*16 + lane>>2
    const int r0 = rowBase + warp * 16 + (lane >> 2);
    const int kp = lane & 3;
    const float* aP[3];
    #pragma unroll
    for (int c = 0; c < 3; c++)
        aP[c] = Ap[c] + (size_t)r0 * N_ + kp * 2;
    const size_t R8 = (size_t)8 * N_;    // +8 rows

    // T cp.async map: 3 x 16B per thread
    const __half* tSrc[3];
    uint32_t tDst[3];
    #pragma unroll
    for (int j = 0; j < 3; j++) {
        const int id = tid + 256 * j;    // 0..767
        const int c  = id >> 8;
        const int n  = (id >> 2) & 63;
        const int ch = id & 3;
        tSrc[j] = &g_T[c][b][n][0] + ch * 8;
        tDst[j] = (uint32_t)(c * T_CH_B + n * 64 + 16 * (ch ^ ((n >> 1) & 3)));
    }

    #define CP_T(kt, slot) do {                                                \
        const uint32_t _so = sb + (uint32_t)(slot) * STAGE_BYTES;              \
        const int _k0 = (kt) * BK;                                             \
        _Pragma("unroll")                                                      \
        for (int j = 0; j < 3; j++)                                            \
            asm volatile("cp.async.cg.shared.global [%0], [%1], 16;"           \
                         :: "r"(_so + tDst[j]), "l"(tSrc[j] + _k0) : "memory");\
        asm volatile("cp.async.commit_group;" ::: "memory");                   \
    } while (0)

    // A fragment prefetch: 24 float2 (f32 pairs) per k-tile
    float2 pf[3][2][4];
    #define PF_A(kt) do {                                                      \
        _Pragma("unroll")                                                      \
        for (int c = 0; c < 3; c++) {                                          \
            _Pragma("unroll")                                                  \
            for (int ks = 0; ks < 2; ks++) {                                   \
                const int _off = (kt) * BK + ks * 16;                          \
                pf[c][ks][0] = __ldcs((const float2*)(aP[c] + _off));          \
                pf[c][ks][1] = __ldcs((const float2*)(aP[c] + R8 + _off));     \
                pf[c][ks][2] = __ldcs((const float2*)(aP[c] + _off + 8));      \
                pf[c][ks][3] = __ldcs((const float2*)(aP[c] + R8 + _off + 8)); \
            }                                                                  \
        }                                                                      \
    } while (0)

    // B fragment geometry
    const int row16 = lane & 15;
    const int cbit  = lane >> 4;
    const uint32_t swz = (uint32_t)((row16 >> 1) & 3);
    const uint32_t bRowOff = (uint32_t)(row16 * 64);

    float acc[8][4];
    #pragma unroll
    for (int nt = 0; nt < 8; nt++)
        #pragma unroll
        for (int i = 0; i < 4; i++) acc[nt][i] = 0.f;

    // prologue: 3 T stages in flight, A(0) fragments in registers
    CP_T(0, 0);
    CP_T(1, 1);
    CP_T(2, 2);
    PF_A(0);

    for (int s = 0; s < NKT; s++) {
        const int slot = s & 3;
        asm volatile("cp.async.wait_group 2;" ::: "memory");
        __syncthreads();

        // convert current A fragments, freeing pf for next prefetch
        uint32_t af[3][2][4];
        #pragma unroll
        for (int c = 0; c < 3; c++)
            #pragma unroll
            for (int ks = 0; ks < 2; ks++)
                #pragma unroll
                for (int i = 0; i < 4; i++)
                    af[c][ks][i] = packh2(pf[c][ks][i].x, pf[c][ks][i].y);

        if (s + 1 < NKT) PF_A(s + 1);

        // refill T stage s+3 (slot freed by iter s-1)
        if (s + 3 < NKT) {
            CP_T(s + 3, (s + 3) & 3);
        } else {
            asm volatile("cp.async.commit_group;" ::: "memory");
        }

        // compute on T stage s
        const uint32_t stBase = sb + (uint32_t)slot * STAGE_BYTES;
        #pragma unroll
        for (int c = 0; c < 3; c++) {
            const uint32_t bCh = stBase + c * T_CH_B + bRowOff;
            #pragma unroll
            for (int ks = 0; ks < 2; ks++) {
                const uint32_t kch = 16u * ((uint32_t)((ks << 1) | cbit) ^ swz);
                #pragma unroll
                for (int nt = 0; nt < 4; nt++) {
                    uint32_t bb[4];
                    ldsm4(bb, bCh + nt * 1024 + kch);
                    mma16816(acc[2*nt],     af[c][ks], bb[0], bb[2]);
                    mma16816(acc[2*nt + 1], af[c][ks], bb[1], bb[3]);
                }
            }
        }
    }

    // epilogue: relu + store
    #pragma unroll
    for (int nt = 0; nt < 8; nt++) {
        const int rr  = rowBase + warp * 16 + (lane >> 2);
        const int col = nt * 8 + (lane & 3) * 2;
        float2 v0 = make_float2(fmaxf(acc[nt][0], 0.f), fmaxf(acc[nt][1], 0.f));
        float2 v1 = make_float2(fmaxf(acc[nt][2], 0.f), fmaxf(acc[nt][3], 0.f));
        *(float2*)(Y + ((size_t)b * N_ + rr) * F_ + col)     = v0;
        *(float2*)(Y + ((size_t)b * N_ + rr + 8) * F_ + col) = v1;
    }
}

// ---------------------------------------------------------------------------
extern "C" void kernel_launch(void* const* d_in, const int* in_sizes, int n_in,
                              void* d_out, int out_size) {
    (void)in_sizes; (void)n_in; (void)out_size;
    const float* X  = (const float*)d_in[0];
    const float* A0 = (const float*)d_in[1];
    const float* A1 = (const float*)d_in[2];
    const float* A2 = (const float*)d_in[3];
    const float* w0 = (const float*)d_in[4];
    const float* w1 = (const float*)d_in[5];
    const float* w2 = (const float*)d_in[6];
    float* Y = (float*)d_out;

    dim3 g1(N_ / 64, B_, 3);
    compute_T_kernel<<<g1, 256>>>(X, w0, w1, w2);

    cudaFuncSetAttribute(gnn_main_kernel,
                         cudaFuncAttributeMaxDynamicSharedMemorySize, SMEM_BYTES);
    dim3 g2(N_ / BM, B_);
    gnn_main_kernel<<<g2, 256, SMEM_BYTES>>>(A0, A1, A2, Y);
}

// round 8
// speedup vs baseline: 1.1318x; 1.1318x over previous
#include <cuda_runtime.h>
#include <cuda_fp16.h>
#include <cstdint>

#define B_ 4
#define N_ 4096
#define F_ 64
#define BM 128
#define BK 32
#define NKT (N_ / BK)                  // 128
#define STAGES 4

// smem: T-only ring. One stage = 3 chains x 64 rows x 64B = 12288 B.
#define T_CH_B (F_ * 64)               // 4096
#define STAGE_BYTES (3 * T_CH_B)       // 12288
#define SMEM_BYTES (STAGES * STAGE_BYTES)   // 49152

// T scratch: g_T[c][b][n][k] = fp16_rne( (X[b] @ w_c)[k][n] )
__device__ __half g_T[3][B_][F_][N_];

// ---------------------------------------------------------------------------
__device__ __forceinline__ uint32_t smem_u32(const void* p) {
    uint32_t a;
    asm("{ .reg .u64 t; cvta.to.shared.u64 t, %1; cvt.u32.u64 %0, t; }"
        : "=r"(a) : "l"(p));
    return a;
}
__device__ __forceinline__ void ldsm4(uint32_t* r, uint32_t addr) {
    asm volatile("ldmatrix.sync.aligned.m8n8.x4.shared.b16 {%0,%1,%2,%3}, [%4];"
                 : "=r"(r[0]), "=r"(r[1]), "=r"(r[2]), "=r"(r[3]) : "r"(addr));
}
__device__ __forceinline__ void mma16816(float* d, const uint32_t* a,
                                         uint32_t b0, uint32_t b1) {
    asm volatile("mma.sync.aligned.m16n8k16.row.col.f32.f16.f16.f32 "
                 "{%0,%1,%2,%3}, {%4,%5,%6,%7}, {%8,%9}, {%0,%1,%2,%3};"
                 : "+f"(d[0]), "+f"(d[1]), "+f"(d[2]), "+f"(d[3])
                 : "r"(a[0]), "r"(a[1]), "r"(a[2]), "r"(a[3]), "r"(b0), "r"(b1));
}
__device__ __forceinline__ uint32_t packh2(float x, float y) {
    __half2 h = __floats2half2_rn(x, y);
    return *(uint32_t*)&h;
}

// ---------------------------------------------------------------------------
// Kernel 1: g_T[c][b][g][m] = fp16( sum_f X[b][m][f] * w_c[f][g] )
// ---------------------------------------------------------------------------
__global__ void __launch_bounds__(256)
compute_T_kernel(const float* __restrict__ X,
                 const float* __restrict__ w0,
                 const float* __restrict__ w1,
                 const float* __restrict__ w2) {
    const int c = blockIdx.z;
    const int b = blockIdx.y;
    const int m0 = blockIdx.x * 64;
    const float* w = (c == 0) ? w0 : (c == 1) ? w1 : w2;

    __shared__ float sX[64 * 68];
    __shared__ float sW[64 * 68];

    const int tid = threadIdx.x;
    {
        const int q = tid & 15;
        const int r = tid >> 4;
        #pragma unroll
        for (int j = 0; j < 4; j++) {
            const int row = r + 16 * j;
            *(float4*)(sX + row * 68 + q * 4) =
                *(const float4*)(X + ((size_t)b * N_ + m0 + row) * F_ + q * 4);
            *(float4*)(sW + row * 68 + q * 4) =
                *(const float4*)(w + (size_t)row * F_ + q * 4);
        }
    }
    __syncthreads();

    const int row = tid & 63;            // distinct per lane -> 1 wavefront
    const int g0  = (tid >> 6) * 16;     // uniform per warp -> broadcast

    float acc[16];
    #pragma unroll
    for (int i = 0; i < 16; i++) acc[i] = 0.f;

    #pragma unroll 8
    for (int f = 0; f < 64; f++) {
        const float x = sX[row * 68 + f];
        #pragma unroll
        for (int j = 0; j < 4; j++) {
            float4 wv = *(const float4*)(sW + f * 68 + g0 + j * 4);
            acc[j * 4 + 0] += x * wv.x;
            acc[j * 4 + 1] += x * wv.y;
            acc[j * 4 + 2] += x * wv.z;
            acc[j * 4 + 3] += x * wv.w;
        }
    }
    __syncthreads();

    #pragma unroll
    for (int j = 0; j < 4; j++)
        *(float4*)(sX + row * 68 + g0 + j * 4) =
            make_float4(acc[j*4+0], acc[j*4+1], acc[j*4+2], acc[j*4+3]);
    __syncthreads();

    const int g  = tid >> 2;
    const int ms = (tid & 3) * 16;
    uint32_t h[8];
    #pragma unroll
    for (int i = 0; i < 8; i++)
        h[i] = packh2(sX[(ms + 2*i) * 68 + g], sX[(ms + 2*i + 1) * 68 + g]);
    __half* out = &g_T[c][b][g][m0 + ms];
    ((uint4*)out)[0] = make_uint4(h[0], h[1], h[2], h[3]);
    ((uint4*)out)[1] = make_uint4(h[4], h[5], h[6], h[7]);
}

// ---------------------------------------------------------------------------
// Kernel 2: Y[b] = relu(A0@T0 + A1@T1 + A2@T2)
// grid (32, 4) = 128 CTAs, block 256 (8 warps, warp tile 16x64).
// A: direct GMEM->register, DOUBLE-buffered 2 k-tiles ahead (no smem, no STS).
// T: 4-stage cp.async smem ring + ldmatrix.
// ---------------------------------------------------------------------------
__global__ void __launch_bounds__(256)
gnn_main_kernel(const float* __restrict__ A0,
                const float* __restrict__ A1,
                const float* __restrict__ A2,
                float* __restrict__ Y) {
    extern __shared__ char smem[];
    const uint32_t sb = smem_u32(smem);
    const int tid = threadIdx.x;
    const int b = blockIdx.y;
    const int rowBase = blockIdx.x * BM;

    const int lane = tid & 31;
    const int warp = tid >> 5;

    // per-warp A fragment pointers: row r0 = rowBase + warp*16 + lane>>2
    const int r0 = rowBase + warp * 16 + (lane >> 2);
    const int kp = lane & 3;
    const float* aP[3];
    aP[0] = A0 + (size_t)b * N_ * N_ + (size_t)r0 * N_ + kp * 2;
    aP[1] = A1 + (size_t)b * N_ * N_ + (size_t)r0 * N_ + kp * 2;
    aP[2] = A2 + (size_t)b * N_ * N_ + (size_t)r0 * N_ + kp * 2;
    const size_t R8 = (size_t)8 * N_;    // +8 rows

    // T cp.async map: 3 x 16B per thread
    const __half* tSrc[3];
    uint32_t tDst[3];
    #pragma unroll
    for (int j = 0; j < 3; j++) {
        const int id = tid + 256 * j;    // 0..767
        const int c  = id >> 8;
        const int n  = (id >> 2) & 63;
        const int ch = id & 3;
        tSrc[j] = &g_T[c][b][n][0] + ch * 8;
        tDst[j] = (uint32_t)(c * T_CH_B + n * 64 + 16 * (ch ^ ((n >> 1) & 3)));
    }

    #define CP_T(kt, slot) do {                                                \
        const uint32_t _so = sb + (uint32_t)(slot) * STAGE_BYTES;              \
        const int _k0 = (kt) * BK;                                             \
        _Pragma("unroll")                                                      \
        for (int j = 0; j < 3; j++)                                            \
            asm volatile("cp.async.cg.shared.global [%0], [%1], 16;"           \
                         :: "r"(_so + tDst[j]), "l"(tSrc[j] + _k0) : "memory");\
        asm volatile("cp.async.commit_group;" ::: "memory");                   \
    } while (0)

    // one chain's A fragments for one k-tile: 8 float2 (fp32 pairs)
    #define PF_CH(dst, c, kt) do {                                             \
        const int _o = (kt) * BK;                                              \
        (dst)[0] = __ldcs((const float2*)(aP[c] + _o));                        \
        (dst)[1] = __ldcs((const float2*)(aP[c] + R8 + _o));                   \
        (dst)[2] = __ldcs((const float2*)(aP[c] + _o + 8));                    \
        (dst)[3] = __ldcs((const float2*)(aP[c] + R8 + _o + 8));               \
        (dst)[4] = __ldcs((const float2*)(aP[c] + _o + 16));                   \
        (dst)[5] = __ldcs((const float2*)(aP[c] + R8 + _o + 16));              \
        (dst)[6] = __ldcs((const float2*)(aP[c] + _o + 24));                   \
        (dst)[7] = __ldcs((const float2*)(aP[c] + R8 + _o + 24));              \
    } while (0)

    // B fragment geometry
    const int row16 = lane & 15;
    const int cbit  = lane >> 4;
    const uint32_t swz = (uint32_t)((row16 >> 1) & 3);
    const uint32_t bRowOff = (uint32_t)(row16 * 64);

    float acc[8][4];
    #pragma unroll
    for (int nt = 0; nt < 8; nt++)
        #pragma unroll
        for (int i = 0; i < 4; i++) acc[nt][i] = 0.f;

    // double-buffered A prefetch: pf[ph][chain][8]
    float2 pf[2][3][8];

    // prologue: 3 T stages in flight; A(0)->pf[0], A(1)->pf[1]
    CP_T(0, 0);
    CP_T(1, 1);
    CP_T(2, 2);
    #pragma unroll
    for (int c = 0; c < 3; c++) PF_CH(pf[0][c], c, 0);
    #pragma unroll
    for (int c = 0; c < 3; c++) PF_CH(pf[1][c], c, 1);

    for (int s2 = 0; s2 < NKT; s2 += 2) {
        #pragma unroll
        for (int ph = 0; ph < 2; ph++) {
            const int s = s2 + ph;
            asm volatile("cp.async.wait_group 2;" ::: "memory");
            __syncthreads();

            const uint32_t stBase = sb + (uint32_t)(s & 3) * STAGE_BYTES;
            #pragma unroll
            for (int c = 0; c < 3; c++) {
                // convert this chain's fragments (loaded 2 iters ago -> ready)
                uint32_t af[2][4];
                #pragma unroll
                for (int ks = 0; ks < 2; ks++)
                    #pragma unroll
                    for (int i = 0; i < 4; i++) {
                        float2 v = pf[ph][c][ks * 4 + i];
                        af[ks][i] = packh2(v.x, v.y);
                    }
                // refill this chain's buffer for k-tile s+2 (consumed 2 iters later)
                if (s + 2 < NKT) PF_CH(pf[ph][c], c, s + 2);

                // compute chain c on T stage s
                const uint32_t bCh = stBase + c * T_CH_B + bRowOff;
                #pragma unroll
                for (int ks = 0; ks < 2; ks++) {
                    const uint32_t kch = 16u * ((uint32_t)((ks << 1) | cbit) ^ swz);
                    #pragma unroll
                    for (int nt = 0; nt < 4; nt++) {
                        uint32_t bb[4];
                        ldsm4(bb, bCh + nt * 1024 + kch);
                        mma16816(acc[2*nt],     af[ks], bb[0], bb[2]);
                        mma16816(acc[2*nt + 1], af[ks], bb[1], bb[3]);
                    }
                }
            }

            // refill T stage s+3 (slot freed by iter s-1)
            if (s + 3 < NKT) {
                CP_T(s + 3, (s + 3) & 3);
            } else {
                asm volatile("cp.async.commit_group;" ::: "memory");
            }
        }
    }

    // epilogue: relu + store
    #pragma unroll
    for (int nt = 0; nt < 8; nt++) {
        const int rr  = rowBase + warp * 16 + (lane >> 2);
        const int col = nt * 8 + (lane & 3) * 2;
        float2 v0 = make_float2(fmaxf(acc[nt][0], 0.f), fmaxf(acc[nt][1], 0.f));
        float2 v1 = make_float2(fmaxf(acc[nt][2], 0.f), fmaxf(acc[nt][3], 0.f));
        *(float2*)(Y + ((size_t)b * N_ + rr) * F_ + col)     = v0;
        *(float2*)(Y + ((size_t)b * N_ + rr + 8) * F_ + col) = v1;
    }
}

// ---------------------------------------------------------------------------
extern "C" void kernel_launch(void* const* d_in, const int* in_sizes, int n_in,
                              void* d_out, int out_size) {
    (void)in_sizes; (void)n_in; (void)out_size;
    const float* X  = (const float*)d_in[0];
    const float* A0 = (const float*)d_in[1];
    const float* A1 = (const float*)d_in[2];
    const float* A2 = (const float*)d_in[3];
    const float* w0 = (const float*)d_in[4];
    const float* w1 = (const float*)d_in[5];
    const float* w2 = (const float*)d_in[6];
    float* Y = (float*)d_out;

    dim3 g1(N_ / 64, B_, 3);
    compute_T_kernel<<<g1, 256>>>(X, w0, w1, w2);

    cudaFuncSetAttribute(gnn_main_kernel,
                         cudaFuncAttributeMaxDynamicSharedMemorySize, SMEM_BYTES);
    dim3 g2(N_ / BM, B_);
    gnn_main_kernel<<<g2, 256, SMEM_BYTES>>>(A0, A1, A2, Y);
}

// round 10
// speedup vs baseline: 1.3770x; 1.2166x over previous
#include <cuda_runtime.h>
#include <cuda_fp16.h>
#include <cstdint>

#define B_ 4
#define N_ 4096
#define F_ 64
#define BM 128
#define BK 32
#define NKT (N_ / BK)                  // 128

// smem: warp-private A double buffers + 12-stage (3-group) T ring
#define A_WARP_ST 3072                 // 3 chains x 16 rows x 64B fp16
#define A_REGION (8 * 2 * A_WARP_ST)   // 49152
#define T_ST_B 12288                   // 3 chains x 64 rows x 64B fp16
#define T_STAGES 12
#define T_REGION (T_STAGES * T_ST_B)   // 147456
#define SMEM_BYTES (A_REGION + T_REGION)   // 196608

// T scratch: g_T[c][b][n][k] = fp16_rne( (X[b] @ w_c)[k][n] )
__device__ __half g_T[3][B_][F_][N_];

// ---------------------------------------------------------------------------
__device__ __forceinline__ uint32_t smem_u32(const void* p) {
    uint32_t a;
    asm("{ .reg .u64 t; cvta.to.shared.u64 t, %1; cvt.u32.u64 %0, t; }"
        : "=r"(a) : "l"(p));
    return a;
}
__device__ __forceinline__ void ldsm4(uint32_t* r, uint32_t addr) {
    asm volatile("ldmatrix.sync.aligned.m8n8.x4.shared.b16 {%0,%1,%2,%3}, [%4];"
                 : "=r"(r[0]), "=r"(r[1]), "=r"(r[2]), "=r"(r[3]) : "r"(addr));
}
__device__ __forceinline__ void mma16816(float* d, const uint32_t* a,
                                         uint32_t b0, uint32_t b1) {
    asm volatile("mma.sync.aligned.m16n8k16.row.col.f32.f16.f16.f32 "
                 "{%0,%1,%2,%3}, {%4,%5,%6,%7}, {%8,%9}, {%0,%1,%2,%3};"
                 : "+f"(d[0]), "+f"(d[1]), "+f"(d[2]), "+f"(d[3])
                 : "r"(a[0]), "r"(a[1]), "r"(a[2]), "r"(a[3]), "r"(b0), "r"(b1));
}
__device__ __forceinline__ uint32_t packh2(float x, float y) {
    __half2 h = __floats2half2_rn(x, y);
    return *(uint32_t*)&h;
}
__device__ __forceinline__ void sts64(uint32_t addr, uint32_t a, uint32_t b) {
    asm volatile("st.shared.v2.b32 [%0], {%1,%2};" :: "r"(addr), "r"(a), "r"(b)
                 : "memory");
}

// ---------------------------------------------------------------------------
// Kernel 1: g_T[c][b][g][m] = fp16( sum_f X[b][m][f] * w_c[f][g] )
// ---------------------------------------------------------------------------
__global__ void __launch_bounds__(256)
compute_T_kernel(const float* __restrict__ X,
                 const float* __restrict__ w0,
                 const float* __restrict__ w1,
                 const float* __restrict__ w2) {
    const int c = blockIdx.z;
    const int b = blockIdx.y;
    const int m0 = blockIdx.x * 64;
    const float* w = (c == 0) ? w0 : (c == 1) ? w1 : w2;

    __shared__ float sX[64 * 68];
    __shared__ float sW[64 * 68];

    const int tid = threadIdx.x;
    {
        const int q = tid & 15;
        const int r = tid >> 4;
        #pragma unroll
        for (int j = 0; j < 4; j++) {
            const int row = r + 16 * j;
            *(float4*)(sX + row * 68 + q * 4) =
                *(const float4*)(X + ((size_t)b * N_ + m0 + row) * F_ + q * 4);
            *(float4*)(sW + row * 68 + q * 4) =
                *(const float4*)(w + (size_t)row * F_ + q * 4);
        }
    }
    __syncthreads();

    const int row = tid & 63;
    const int g0  = (tid >> 6) * 16;

    float acc[16];
    #pragma unroll
    for (int i = 0; i < 16; i++) acc[i] = 0.f;

    #pragma unroll 8
    for (int f = 0; f < 64; f++) {
        const float x = sX[row * 68 + f];
        #pragma unroll
        for (int j = 0; j < 4; j++) {
            float4 wv = *(const float4*)(sW + f * 68 + g0 + j * 4);
            acc[j * 4 + 0] += x * wv.x;
            acc[j * 4 + 1] += x * wv.y;
            acc[j * 4 + 2] += x * wv.z;
            acc[j * 4 + 3] += x * wv.w;
        }
    }
    __syncthreads();

    #pragma unroll
    for (int j = 0; j < 4; j++)
        *(float4*)(sX + row * 68 + g0 + j * 4) =
            make_float4(acc[j*4+0], acc[j*4+1], acc[j*4+2], acc[j*4+3]);
    __syncthreads();

    const int g  = tid >> 2;
    const int ms = (tid & 3) * 16;
    uint32_t h[8];
    #pragma unroll
    for (int i = 0; i < 8; i++)
        h[i] = packh2(sX[(ms + 2*i) * 68 + g], sX[(ms + 2*i + 1) * 68 + g]);
    __half* out = &g_T[c][b][g][m0 + ms];
    ((uint4*)out)[0] = make_uint4(h[0], h[1], h[2], h[3]);
    ((uint4*)out)[1] = make_uint4(h[4], h[5], h[6], h[7]);
}

// ---------------------------------------------------------------------------
// Kernel 2: Y[b] = relu(A0@T0 + A1@T1 + A2@T2)
// grid (32, 4), block 256 (8 warps, warp tile 16x64).
// A: warp-local LDG->cvt->STS double buffer (syncwarp only, ~2-iter LDG slack).
// T: 12-stage (3-group) cp.async ring; group refill at super-iter TOP, after
//    the block barrier, targeting slots last read one super-iter earlier
//    (race-free); block barrier once per 4 k-tiles.
// ---------------------------------------------------------------------------
__global__ void __launch_bounds__(256)
gnn_main_kernel(const float* __restrict__ A0,
                const float* __restrict__ A1,
                const float* __restrict__ A2,
                float* __restrict__ Y) {
    extern __shared__ char smem[];
    const uint32_t sbA = smem_u32(smem);
    const uint32_t sbT = sbA + A_REGION;
    const int tid = threadIdx.x;
    const int b = blockIdx.y;
    const int rowBase = blockIdx.x * BM;
    const int lane = tid & 31;
    const int warp = tid >> 5;

    const float* Abase[3];
    Abase[0] = A0 + (size_t)b * N_ * N_;
    Abase[1] = A1 + (size_t)b * N_ * N_;
    Abase[2] = A2 + (size_t)b * N_ * N_;

    // A LDG/STS map (warp-local): 12 units of 16B fp32 per lane per k-tile
    const float* aSrc[12];
    uint32_t aDst[12];   // relative to warp-slot base
    #pragma unroll
    for (int u = 0; u < 12; u++) {
        const int id = lane + 32 * u;
        const int rl = id >> 3;           // 0..47 = chain*16 + r
        const int c  = rl >> 4;
        const int r  = rl & 15;
        const int ch = id & 7;            // 16B fp32 unit within 128B row
        aSrc[u] = Abase[c] + (size_t)(rowBase + warp * 16 + r) * N_ + ch * 4;
        aDst[u] = (uint32_t)(c * 1024 + r * 64
                             + (((ch >> 1) ^ ((r >> 1) & 3)) << 4) + (ch & 1) * 8);
    }
    const uint32_t aSlotBase = sbA + warp * (2 * A_WARP_ST);

    // T cp.async map: 3 x 16B per thread per k-tile
    const __half* tSrc[3];
    uint32_t tDst[3];
    #pragma unroll
    for (int j = 0; j < 3; j++) {
        const int id = tid + 256 * j;
        const int c  = id >> 8;
        const int n  = (id >> 2) & 63;
        const int ch = id & 3;
        tSrc[j] = &g_T[c][b][n][0] + ch * 8;
        tDst[j] = (uint32_t)(c * 4096 + n * 64 + 16 * (ch ^ ((n >> 1) & 3)));
    }

    // T stage slot for k-tile kt: group (kt/4)%3, phase kt&3
    #define CP_T1(kt) do {                                                     \
        const uint32_t _slot = (uint32_t)((((kt) >> 2) % 3) * 4 + ((kt) & 3)); \
        const uint32_t _so = sbT + _slot * T_ST_B;                             \
        const int _k0 = (kt) * BK;                                             \
        _Pragma("unroll")                                                      \
        for (int j = 0; j < 3; j++)                                            \
            asm volatile("cp.async.cg.shared.global [%0], [%1], 16;"           \
                         :: "r"(_so + tDst[j]), "l"(tSrc[j] + _k0) : "memory");\
    } while (0)

    #define LDG_A(buf, kt) do {                                                \
        const int _k0 = (kt) * BK;                                             \
        _Pragma("unroll")                                                      \
        for (int u = 0; u < 12; u++)                                           \
            (buf)[u] = __ldcs((const float4*)(aSrc[u] + _k0));                 \
    } while (0)

    #define STS_A(buf, slot) do {                                              \
        const uint32_t _sb2 = aSlotBase + (uint32_t)(slot) * A_WARP_ST;        \
        _Pragma("unroll")                                                      \
        for (int u = 0; u < 12; u++) {                                         \
            float4 v = (buf)[u];                                               \
            sts64(_sb2 + aDst[u], packh2(v.x, v.y), packh2(v.z, v.w));         \
        }                                                                      \
    } while (0)

    // fragment geometry
    const int row16 = lane & 15;
    const int cbit  = lane >> 4;
    const uint32_t swz = (uint32_t)((row16 >> 1) & 3);
    const uint32_t aFrag = (uint32_t)(row16 * 64);
    const uint32_t bFrag = (uint32_t)(row16 * 64);

    float acc[8][4];
    #pragma unroll
    for (int nt = 0; nt < 8; nt++)
        #pragma unroll
        for (int i = 0; i < 4; i++) acc[nt][i] = 0.f;

    float4 bufA[2][12];

    // prologue: A(0),A(1) in regs; T groups 0 (kt 0-3) and 1 (kt 4-7) committed
    LDG_A(bufA[0], 0);
    LDG_A(bufA[1], 1);
    CP_T1(0); CP_T1(1); CP_T1(2); CP_T1(3);
    asm volatile("cp.async.commit_group;" ::: "memory");
    CP_T1(4); CP_T1(5); CP_T1(6); CP_T1(7);
    asm volatile("cp.async.commit_group;" ::: "memory");
    STS_A(bufA[0], 0);
    __syncwarp();

    for (int S = 0; S < NKT / 4; S++) {           // 32 super-iterations
        // group S complete (groups retire in commit order; always-commit below
        // keeps the pending count honest through the tail)
        asm volatile("cp.async.wait_group 1;" ::: "memory");
        __syncthreads();

        // refill group S+2 into slots ((S+2)%3) — last read in super-iter S-1,
        // and every warp passed that read at the barrier above. Race-free.
        if (4 * (S + 2) < NKT) {
            CP_T1(4*S + 8); CP_T1(4*S + 9); CP_T1(4*S + 10); CP_T1(4*S + 11);
        }
        asm volatile("cp.async.commit_group;" ::: "memory");

        const uint32_t grpT = sbT + (uint32_t)((S % 3) * 4) * T_ST_B;
        #pragma unroll
        for (int ph = 0; ph < 4; ph++) {
            const int s = 4 * S + ph;

            // prefetch A(s+2) into the register buffer freed by last phase's STS
            if (s + 2 < NKT) LDG_A(bufA[s & 1], s + 2);

            // compute k-tile s: A slot s&1, T stage (S%3)*4 + ph
            const uint32_t stA = aSlotBase + (uint32_t)(s & 1) * A_WARP_ST;
            const uint32_t stT = grpT + (uint32_t)ph * T_ST_B;
            #pragma unroll
            for (int c = 0; c < 3; c++) {
                const uint32_t aCh = stA + c * 1024 + aFrag;
                const uint32_t bCh = stT + c * 4096 + bFrag;
                #pragma unroll
                for (int ks = 0; ks < 2; ks++) {
                    const uint32_t kch = 16u * ((uint32_t)((ks << 1) | cbit) ^ swz);
                    uint32_t af[4];
                    ldsm4(af, aCh + kch);
                    #pragma unroll
                    for (int nt = 0; nt < 4; nt++) {
                        uint32_t bb[4];
                        ldsm4(bb, bCh + nt * 1024 + kch);
                        mma16816(acc[2*nt],     af, bb[0], bb[2]);
                        mma16816(acc[2*nt + 1], af, bb[1], bb[3]);
                    }
                }
            }

            // stage A(s+1) (warp-private slot; loaded 2 phases ago)
            if (s + 1 < NKT) STS_A(bufA[(s + 1) & 1], (s + 1) & 1);
            __syncwarp();
        }
    }

    // epilogue: relu + store
    #pragma unroll
    for (int nt = 0; nt < 8; nt++) {
        const int rr  = rowBase + warp * 16 + (lane >> 2);
        const int col = nt * 8 + (lane & 3) * 2;
        float2 v0 = make_float2(fmaxf(acc[nt][0], 0.f), fmaxf(acc[nt][1], 0.f));
        float2 v1 = make_float2(fmaxf(acc[nt][2], 0.f), fmaxf(acc[nt][3], 0.f));
        *(float2*)(Y + ((size_t)b * N_ + rr) * F_ + col)     = v0;
        *(float2*)(Y + ((size_t)b * N_ + rr + 8) * F_ + col) = v1;
    }
}

// ---------------------------------------------------------------------------
extern "C" void kernel_launch(void* const* d_in, const int* in_sizes, int n_in,
                              void* d_out, int out_size) {
    (void)in_sizes; (void)n_in; (void)out_size;
    const float* X  = (const float*)d_in[0];
    const float* A0 = (const float*)d_in[1];
    const float* A1 = (const float*)d_in[2];
    const float* A2 = (const float*)d_in[3];
    const float* w0 = (const float*)d_in[4];
    const float* w1 = (const float*)d_in[5];
    const float* w2 = (const float*)d_in[6];
    float* Y = (float*)d_out;

    dim3 g1(N_ / 64, B_, 3);
    compute_T_kernel<<<g1, 256>>>(X, w0, w1, w2);

    cudaFuncSetAttribute(gnn_main_kernel,
                         cudaFuncAttributeMaxDynamicSharedMemorySize, SMEM_BYTES);
    dim3 g2(N_ / BM, B_);
    gnn_main_kernel<<<g2, 256, SMEM_BYTES>>>(A0, A1, A2, Y);
}

// round 11
// speedup vs baseline: 1.3902x; 1.0096x over previous
#include <cuda_runtime.h>
#include <cuda_fp16.h>
#include <cstdint>

#define B_ 4
#define N_ 4096
#define F_ 64
#define BM 64
#define BK 32
#define NKT (N_ / BK)                  // 128

// smem: warp-private A double buffers (4 warps) + 6-stage (3-group x 2) T ring
#define A_WARP_ST 3072                 // 3 chains x 16 rows x 64B fp16
#define A_REGION (4 * 2 * A_WARP_ST)   // 24576
#define T_ST_B 12288                   // 3 chains x 64 rows x 64B fp16
#define T_STAGES 6
#define T_REGION (T_STAGES * T_ST_B)   // 73728
#define SMEM_BYTES (A_REGION + T_REGION)   // 98304 -> 2 CTAs/SM

// T scratch: g_T[c][b][n][k] = fp16_rne( (X[b] @ w_c)[k][n] )
__device__ __half g_T[3][B_][F_][N_];

// ---------------------------------------------------------------------------
__device__ __forceinline__ uint32_t smem_u32(const void* p) {
    uint32_t a;
    asm("{ .reg .u64 t; cvta.to.shared.u64 t, %1; cvt.u32.u64 %0, t; }"
        : "=r"(a) : "l"(p));
    return a;
}
__device__ __forceinline__ void ldsm4(uint32_t* r, uint32_t addr) {
    asm volatile("ldmatrix.sync.aligned.m8n8.x4.shared.b16 {%0,%1,%2,%3}, [%4];"
                 : "=r"(r[0]), "=r"(r[1]), "=r"(r[2]), "=r"(r[3]) : "r"(addr));
}
__device__ __forceinline__ void mma16816(float* d, const uint32_t* a,
                                         uint32_t b0, uint32_t b1) {
    asm volatile("mma.sync.aligned.m16n8k16.row.col.f32.f16.f16.f32 "
                 "{%0,%1,%2,%3}, {%4,%5,%6,%7}, {%8,%9}, {%0,%1,%2,%3};"
                 : "+f"(d[0]), "+f"(d[1]), "+f"(d[2]), "+f"(d[3])
                 : "r"(a[0]), "r"(a[1]), "r"(a[2]), "r"(a[3]), "r"(b0), "r"(b1));
}
__device__ __forceinline__ uint32_t packh2(float x, float y) {
    __half2 h = __floats2half2_rn(x, y);
    return *(uint32_t*)&h;
}
__device__ __forceinline__ void sts64(uint32_t addr, uint32_t a, uint32_t b) {
    asm volatile("st.shared.v2.b32 [%0], {%1,%2};" :: "r"(addr), "r"(a), "r"(b)
                 : "memory");
}

// ---------------------------------------------------------------------------
// Kernel 1: g_T[c][b][g][m] = fp16( sum_f X[b][m][f] * w_c[f][g] )
// ---------------------------------------------------------------------------
__global__ void __launch_bounds__(256)
compute_T_kernel(const float* __restrict__ X,
                 const float* __restrict__ w0,
                 const float* __restrict__ w1,
                 const float* __restrict__ w2) {
    const int c = blockIdx.z;
    const int b = blockIdx.y;
    const int m0 = blockIdx.x * 64;
    const float* w = (c == 0) ? w0 : (c == 1) ? w1 : w2;

    __shared__ float sX[64 * 68];
    __shared__ float sW[64 * 68];

    const int tid = threadIdx.x;
    {
        const int q = tid & 15;
        const int r = tid >> 4;
        #pragma unroll
        for (int j = 0; j < 4; j++) {
            const int row = r + 16 * j;
            *(float4*)(sX + row * 68 + q * 4) =
                *(const float4*)(X + ((size_t)b * N_ + m0 + row) * F_ + q * 4);
            *(float4*)(sW + row * 68 + q * 4) =
                *(const float4*)(w + (size_t)row * F_ + q * 4);
        }
    }
    __syncthreads();

    const int row = tid & 63;
    const int g0  = (tid >> 6) * 16;

    float acc[16];
    #pragma unroll
    for (int i = 0; i < 16; i++) acc[i] = 0.f;

    #pragma unroll 8
    for (int f = 0; f < 64; f++) {
        const float x = sX[row * 68 + f];
        #pragma unroll
        for (int j = 0; j < 4; j++) {
            float4 wv = *(const float4*)(sW + f * 68 + g0 + j * 4);
            acc[j * 4 + 0] += x * wv.x;
            acc[j * 4 + 1] += x * wv.y;
            acc[j * 4 + 2] += x * wv.z;
            acc[j * 4 + 3] += x * wv.w;
        }
    }
    __syncthreads();

    #pragma unroll
    for (int j = 0; j < 4; j++)
        *(float4*)(sX + row * 68 + g0 + j * 4) =
            make_float4(acc[j*4+0], acc[j*4+1], acc[j*4+2], acc[j*4+3]);
    __syncthreads();

    const int g  = tid >> 2;
    const int ms = (tid & 3) * 16;
    uint32_t h[8];
    #pragma unroll
    for (int i = 0; i < 8; i++)
        h[i] = packh2(sX[(ms + 2*i) * 68 + g], sX[(ms + 2*i + 1) * 68 + g]);
    __half* out = &g_T[c][b][g][m0 + ms];
    ((uint4*)out)[0] = make_uint4(h[0], h[1], h[2], h[3]);
    ((uint4*)out)[1] = make_uint4(h[4], h[5], h[6], h[7]);
}

// ---------------------------------------------------------------------------
// Kernel 2: Y[b] = relu(A0@T0 + A1@T1 + A2@T2)
// grid (64, 4) = 256 CTAs, block 128 (4 warps, warp tile 16x64), 2 CTAs/SM.
// A: warp-local LDG->cvt->STS double buffer (syncwarp only).
// T: 6-stage (3-group x 2) cp.async ring; refill group S+2 at super-iter top,
//    after the block barrier (race-free); barrier every 2 k-tiles.
// ---------------------------------------------------------------------------
__global__ void __launch_bounds__(128, 2)
gnn_main_kernel(const float* __restrict__ A0,
                const float* __restrict__ A1,
                const float* __restrict__ A2,
                float* __restrict__ Y) {
    extern __shared__ char smem[];
    const uint32_t sbA = smem_u32(smem);
    const uint32_t sbT = sbA + A_REGION;
    const int tid = threadIdx.x;
    const int b = blockIdx.y;
    const int rowBase = blockIdx.x * BM;
    const int lane = tid & 31;
    const int warp = tid >> 5;

    const float* Abase[3];
    Abase[0] = A0 + (size_t)b * N_ * N_;
    Abase[1] = A1 + (size_t)b * N_ * N_;
    Abase[2] = A2 + (size_t)b * N_ * N_;

    // A LDG/STS map (warp-local): 12 units of 16B fp32 per lane per k-tile
    const float* aSrc[12];
    uint32_t aDst[12];
    #pragma unroll
    for (int u = 0; u < 12; u++) {
        const int id = lane + 32 * u;
        const int rl = id >> 3;           // 0..47 = chain*16 + r
        const int c  = rl >> 4;
        const int r  = rl & 15;
        const int ch = id & 7;
        aSrc[u] = Abase[c] + (size_t)(rowBase + warp * 16 + r) * N_ + ch * 4;
        aDst[u] = (uint32_t)(c * 1024 + r * 64
                             + (((ch >> 1) ^ ((r >> 1) & 3)) << 4) + (ch & 1) * 8);
    }
    const uint32_t aSlotBase = sbA + warp * (2 * A_WARP_ST);

    // T cp.async map: 6 x 16B per thread per k-tile (128 threads x 6 = 768)
    const __half* tSrc[6];
    uint32_t tDst[6];
    #pragma unroll
    for (int j = 0; j < 6; j++) {
        const int id = tid + 128 * j;
        const int c  = id >> 8;
        const int n  = (id >> 2) & 63;
        const int ch = id & 3;
        tSrc[j] = &g_T[c][b][n][0] + ch * 8;
        tDst[j] = (uint32_t)(c * 4096 + n * 64 + 16 * (ch ^ ((n >> 1) & 3)));
    }

    // T stage slot for k-tile kt: group (kt/2)%3, phase kt&1
    #define CP_T1(kt) do {                                                     \
        const uint32_t _slot = (uint32_t)(((((kt) >> 1) % 3) << 1) + ((kt)&1));\
        const uint32_t _so = sbT + _slot * T_ST_B;                             \
        const int _k0 = (kt) * BK;                                             \
        _Pragma("unroll")                                                      \
        for (int j = 0; j < 6; j++)                                            \
            asm volatile("cp.async.cg.shared.global [%0], [%1], 16;"           \
                         :: "r"(_so + tDst[j]), "l"(tSrc[j] + _k0) : "memory");\
    } while (0)

    #define LDG_A(buf, kt) do {                                                \
        const int _k0 = (kt) * BK;                                             \
        _Pragma("unroll")                                                      \
        for (int u = 0; u < 12; u++)                                           \
            (buf)[u] = __ldcs((const float4*)(aSrc[u] + _k0));                 \
    } while (0)

    #define STS_A(buf, slot) do {                                              \
        const uint32_t _sb2 = aSlotBase + (uint32_t)(slot) * A_WARP_ST;        \
        _Pragma("unroll")                                                      \
        for (int u = 0; u < 12; u++) {                                         \
            float4 v = (buf)[u];                                               \
            sts64(_sb2 + aDst[u], packh2(v.x, v.y), packh2(v.z, v.w));         \
        }                                                                      \
    } while (0)

    // fragment geometry
    const int row16 = lane & 15;
    const int cbit  = lane >> 4;
    const uint32_t swz = (uint32_t)((row16 >> 1) & 3);
    const uint32_t aFrag = (uint32_t)(row16 * 64);
    const uint32_t bFrag = (uint32_t)(row16 * 64);

    float acc[8][4];
    #pragma unroll
    for (int nt = 0; nt < 8; nt++)
        #pragma unroll
        for (int i = 0; i < 4; i++) acc[nt][i] = 0.f;

    float4 bufA[2][12];

    // prologue: A(0),A(1) in regs; T groups 0 (kt 0-1) and 1 (kt 2-3) committed
    LDG_A(bufA[0], 0);
    LDG_A(bufA[1], 1);
    CP_T1(0); CP_T1(1);
    asm volatile("cp.async.commit_group;" ::: "memory");
    CP_T1(2); CP_T1(3);
    asm volatile("cp.async.commit_group;" ::: "memory");
    STS_A(bufA[0], 0);
    __syncwarp();

    for (int S = 0; S < NKT / 2; S++) {           // 64 super-iterations
        asm volatile("cp.async.wait_group 1;" ::: "memory");
        __syncthreads();

        // refill group S+2 (slots last read in super-iter S-1 — race-free)
        if (2 * (S + 2) < NKT) {
            CP_T1(2*S + 4); CP_T1(2*S + 5);
        }
        asm volatile("cp.async.commit_group;" ::: "memory");

        const uint32_t grpT = sbT + (uint32_t)((S % 3) * 2) * T_ST_B;
        #pragma unroll
        for (int ph = 0; ph < 2; ph++) {
            const int s = 2 * S + ph;

            if (s + 2 < NKT) LDG_A(bufA[s & 1], s + 2);

            const uint32_t stA = aSlotBase + (uint32_t)(s & 1) * A_WARP_ST;
            const uint32_t stT = grpT + (uint32_t)ph * T_ST_B;
            #pragma unroll
            for (int c = 0; c < 3; c++) {
                const uint32_t aCh = stA + c * 1024 + aFrag;
                const uint32_t bCh = stT + c * 4096 + bFrag;
                #pragma unroll
                for (int ks = 0; ks < 2; ks++) {
                    const uint32_t kch = 16u * ((uint32_t)((ks << 1) | cbit) ^ swz);
                    uint32_t af[4];
                    ldsm4(af, aCh + kch);
                    #pragma unroll
                    for (int nt = 0; nt < 4; nt++) {
                        uint32_t bb[4];
                        ldsm4(bb, bCh + nt * 1024 + kch);
                        mma16816(acc[2*nt],     af, bb[0], bb[2]);
                        mma16816(acc[2*nt + 1], af, bb[1], bb[3]);
                    }
                }
            }

            if (s + 1 < NKT) STS_A(bufA[(s + 1) & 1], (s + 1) & 1);
            __syncwarp();
        }
    }

    // epilogue: relu + store
    #pragma unroll
    for (int nt = 0; nt < 8; nt++) {
        const int rr  = rowBase + warp * 16 + (lane >> 2);
        const int col = nt * 8 + (lane & 3) * 2;
        float2 v0 = make_float2(fmaxf(acc[nt][0], 0.f), fmaxf(acc[nt][1], 0.f));
        float2 v1 = make_float2(fmaxf(acc[nt][2], 0.f), fmaxf(acc[nt][3], 0.f));
        *(float2*)(Y + ((size_t)b * N_ + rr) * F_ + col)     = v0;
        *(float2*)(Y + ((size_t)b * N_ + rr + 8) * F_ + col) = v1;
    }
}

// ---------------------------------------------------------------------------
extern "C" void kernel_launch(void* const* d_in, const int* in_sizes, int n_in,
                              void* d_out, int out_size) {
    (void)in_sizes; (void)n_in; (void)out_size;
    const float* X  = (const float*)d_in[0];
    const float* A0 = (const float*)d_in[1];
    const float* A1 = (const float*)d_in[2];
    const float* A2 = (const float*)d_in[3];
    const float* w0 = (const float*)d_in[4];
    const float* w1 = (const float*)d_in[5];
    const float* w2 = (const float*)d_in[6];
    float* Y = (float*)d_out;

    dim3 g1(N_ / 64, B_, 3);
    compute_T_kernel<<<g1, 256>>>(X, w0, w1, w2);

    cudaFuncSetAttribute(gnn_main_kernel,
                         cudaFuncAttributeMaxDynamicSharedMemorySize, SMEM_BYTES);
    dim3 g2(N_ / BM, B_);
    gnn_main_kernel<<<g2, 128, SMEM_BYTES>>>(A0, A1, A2, Y);
}